// round 2
// baseline (speedup 1.0000x reference)
#include <cuda_runtime.h>
#include <math.h>
#include <stdint.h>

#define N_NODES 200000
#define E_EDGES 800000
#define NBATCH  16
#define PK      208   // 193 padded up to multiple of 16

// ---------------- scratch (static device allocations; no cudaMalloc) ----------
__device__ float    g_cat [(size_t)N_NODES * PK];
__device__ float    g_x   [(size_t)N_NODES * 128];
__device__ float    g_xp  [(size_t)N_NODES * 128];
__device__ float    g_agg [(size_t)N_NODES * 128];
__device__ float    g_xn  [(size_t)N_NODES * 128];
__device__ float    g_deg [N_NODES];
__device__ float    g_wpad[PK * 128];
__device__ float    g_wstk[256 * 64];
__device__ unsigned g_gmax[NBATCH * 64];
__device__ float    g_gsum[NBATCH * 64];
__device__ float    g_cnt [NBATCH];

// ---------------- helpers ----------------
__device__ __forceinline__ unsigned fenc(float f) {
    unsigned u = __float_as_uint(f);
    return (u & 0x80000000u) ? ~u : (u | 0x80000000u);
}
__device__ __forceinline__ float fdec(unsigned u) {
    return (u & 0x80000000u) ? __uint_as_float(u & 0x7FFFFFFFu) : __uint_as_float(~u);
}

__global__ void zero_f(float* p, size_t n) {
    size_t i = (size_t)blockIdx.x * blockDim.x + threadIdx.x;
    if (i < n) p[i] = 0.f;
}

// zero all pooling accumulators in one kernel (1024 + 1024 + 16 elements)
__global__ void pool_init_kernel() {
    int i = blockIdx.x * blockDim.x + threadIdx.x;
    if (i < NBATCH * 64) {
        g_gmax[i] = 0u;       // 0u == identity for encoded float max
        g_gsum[i] = 0.f;
    }
    if (i < NBATCH) g_cnt[i] = 0.f;
}

// pad lin_w (193x128) -> g_wpad (208x128), zero rows >=193
__global__ void pad_w_kernel(const float* __restrict__ lin_w) {
    int t = blockIdx.x * blockDim.x + threadIdx.x;
    if (t >= PK * 128) return;
    int k = t / 128, j = t % 128;
    g_wpad[t] = (k < 193) ? lin_w[k * 128 + j] : 0.f;
}

// stack [wl; wr] -> g_wstk ((2D)x64)
__global__ void stack_w_kernel(const float* __restrict__ wl, const float* __restrict__ wr, int D) {
    int t = blockIdx.x * blockDim.x + threadIdx.x;
    if (t >= 2 * D * 64) return;
    int k = t / 64, j = t % 64;
    g_wstk[t] = (k < D) ? wl[k * 64 + j] : wr[(k - D) * 64 + j];
}

// build concatenated feature matrix (N x PK): [nf(139) | type_emb(4) | op_emb(32) | cfg(18) | 0-pad]
__global__ void embed_kernel(const float* __restrict__ nf, const float* __restrict__ cfg,
                             const int* __restrict__ opc,
                             const float* __restrict__ opE, const float* __restrict__ tyE) {
    size_t t = (size_t)blockIdx.x * blockDim.x + threadIdx.x;
    if (t >= (size_t)N_NODES * PK) return;
    int n = (int)(t / PK), c = (int)(t % PK);
    float v = 0.f;
    if (c < 139)      v = nf[(size_t)n * 140 + c];
    else if (c < 143) { int ty = (int)nf[(size_t)n * 140 + 139]; v = tyE[ty * 4 + (c - 139)]; }
    else if (c < 175) v = opE[opc[n] * 32 + (c - 143)];
    else if (c < 193) v = cfg[(size_t)n * 18 + (c - 175)];
    g_cat[t] = v;
}

__global__ void deg_kernel(const int* __restrict__ dst) {
    int e = blockIdx.x * blockDim.x + threadIdx.x;
    if (e < E_EDGES) atomicAdd(&g_deg[dst[e]], 1.f);
}
__global__ void deginv_kernel() {
    int n = blockIdx.x * blockDim.x + threadIdx.x;
    if (n < N_NODES) g_deg[n] = 1.f / fmaxf(g_deg[n], 1.f);
}

// agg[dst] += xp[src] * deg_inv[dst], vectorized 4-wide reductions
__global__ void scatter_kernel(const float* __restrict__ xp, const int* __restrict__ src,
                               const int* __restrict__ dst, float* __restrict__ agg, int D4) {
    size_t t = (size_t)blockIdx.x * blockDim.x + threadIdx.x;
    size_t total = (size_t)E_EDGES * D4;
    if (t >= total) return;
    int e = (int)(t / D4), q = (int)(t % D4);
    int s = src[e], d = dst[e];
    float4 v = reinterpret_cast<const float4*>(xp)[(size_t)s * D4 + q];
    float di = g_deg[d];
    float* p = agg + ((size_t)d * D4 + q) * 4;
    asm volatile("red.global.add.v4.f32 [%0], {%1,%2,%3,%4};"
                 :: "l"(p), "f"(v.x * di), "f"(v.y * di), "f"(v.z * di), "f"(v.w * di)
                 : "memory");
}

// ---------------- tiled fp32 GEMM with fused epilogue ----------------
// C[M x BN] = act( [A1 | A2][M x K] @ W[K x BN] + bias ), optional row L2-normalize.
// BM=128, BK=16, 256 threads, micro-tile TM=8 x TN.
template<int BN, int TN, bool RELU, bool NORM>
__global__ __launch_bounds__(256)
void gemm_kernel(const float* __restrict__ A1, int lda1, int K1,
                 const float* __restrict__ A2, int lda2,
                 const float* __restrict__ W, const float* __restrict__ bias,
                 float* __restrict__ C, int ldc, int K) {
    constexpr int BM = 128, BK = 16, TM = 8;
    constexpr int TX = BN / TN;           // 16
    constexpr int NT = TX * (BM / TM);    // 256
    __shared__ float As[BK][BM];
    __shared__ float Bs[BK][BN];
    const int tid = threadIdx.x;
    const int tx = tid % TX, ty = tid / TX;
    const int m0 = blockIdx.x * BM;

    float acc[TM][TN];
#pragma unroll
    for (int i = 0; i < TM; i++)
#pragma unroll
        for (int j = 0; j < TN; j++) acc[i][j] = 0.f;

    for (int k0 = 0; k0 < K; k0 += BK) {
#pragma unroll
        for (int i = 0; i < (BM * BK) / NT; i++) {
            int idx = tid + i * NT;
            int m = idx / BK, k = idx % BK;
            int kg = k0 + k, mg = m0 + m;
            float v = 0.f;
            if (mg < N_NODES) {
                if (kg < K1)       v = A1[(size_t)mg * lda1 + kg];
                else if (kg < K)   v = A2[(size_t)mg * lda2 + (kg - K1)];
            }
            As[k][m] = v;
        }
#pragma unroll
        for (int i = 0; i < (BK * BN) / NT; i++) {
            int idx = tid + i * NT;
            int k = idx / BN, n = idx % BN;
            int kg = k0 + k;
            Bs[k][n] = (kg < K) ? W[(size_t)kg * BN + n] : 0.f;
        }
        __syncthreads();
#pragma unroll
        for (int kk = 0; kk < BK; kk++) {
            float ra[TM], rb[TN];
#pragma unroll
            for (int i = 0; i < TM; i += 4) {
                float4 a = *reinterpret_cast<const float4*>(&As[kk][ty * TM + i]);
                ra[i] = a.x; ra[i + 1] = a.y; ra[i + 2] = a.z; ra[i + 3] = a.w;
            }
#pragma unroll
            for (int j = 0; j < TN; j += 4) {
                float4 b = *reinterpret_cast<const float4*>(&Bs[kk][tx * TN + j]);
                rb[j] = b.x; rb[j + 1] = b.y; rb[j + 2] = b.z; rb[j + 3] = b.w;
            }
#pragma unroll
            for (int i = 0; i < TM; i++)
#pragma unroll
                for (int j = 0; j < TN; j++) acc[i][j] = fmaf(ra[i], rb[j], acc[i][j]);
        }
        __syncthreads();
    }

    float bcol[TN];
#pragma unroll
    for (int j = 0; j < TN; j++) bcol[j] = bias[tx * TN + j];
#pragma unroll
    for (int i = 0; i < TM; i++)
#pragma unroll
        for (int j = 0; j < TN; j++) {
            acc[i][j] += bcol[j];
            if (RELU) acc[i][j] = fmaxf(acc[i][j], 0.f);
        }

    if (NORM) {
#pragma unroll
        for (int i = 0; i < TM; i++) {
            float ss = 0.f;
#pragma unroll
            for (int j = 0; j < TN; j++) ss += acc[i][j] * acc[i][j];
#pragma unroll
            for (int off = TX / 2; off > 0; off >>= 1)
                ss += __shfl_xor_sync(0xffffffffu, ss, off, TX);
            float inv = 1.f / fmaxf(sqrtf(ss), 1e-12f);
#pragma unroll
            for (int j = 0; j < TN; j++) acc[i][j] *= inv;
        }
    }

#pragma unroll
    for (int i = 0; i < TM; i++) {
        int mg = m0 + ty * TM + i;
        if (mg < N_NODES) {
#pragma unroll
            for (int j = 0; j < TN; j += 4) {
                float4 o = make_float4(acc[i][j], acc[i][j + 1], acc[i][j + 2], acc[i][j + 3]);
                *reinterpret_cast<float4*>(&C[(size_t)mg * ldc + tx * TN + j]) = o;
            }
        }
    }
}

// ---------------- pooling ----------------
__global__ void pool_kernel(const float* __restrict__ x, const int* __restrict__ batch) {
    size_t t = (size_t)blockIdx.x * blockDim.x + threadIdx.x;
    if (t >= (size_t)N_NODES * 16) return;
    int n = (int)(t / 16), q = (int)(t % 16);
    int b = batch[n];
    float4 v = reinterpret_cast<const float4*>(x)[(size_t)n * 16 + q];
    int base = b * 64 + q * 4;
    atomicMax(&g_gmax[base + 0], fenc(v.x));
    atomicMax(&g_gmax[base + 1], fenc(v.y));
    atomicMax(&g_gmax[base + 2], fenc(v.z));
    atomicMax(&g_gmax[base + 3], fenc(v.w));
    atomicAdd(&g_gsum[base + 0], v.x);
    atomicAdd(&g_gsum[base + 1], v.y);
    atomicAdd(&g_gsum[base + 2], v.z);
    atomicAdd(&g_gsum[base + 3], v.w);
    if (q == 0) atomicAdd(&g_cnt[b], 1.f);
}

__global__ void final_kernel(const float* __restrict__ pw, const float* __restrict__ pb,
                             float* __restrict__ out) {
    int b = threadIdx.x / 32, lane = threadIdx.x % 32;
    if (b >= NBATCH) return;
    float c = fmaxf(g_cnt[b], 1.f);
    float g0 = fdec(g_gmax[b * 64 + lane])      + g_gsum[b * 64 + lane] / c;
    float g1 = fdec(g_gmax[b * 64 + lane + 32]) + g_gsum[b * 64 + lane + 32] / c;
    float ss = g0 * g0 + g1 * g1;
#pragma unroll
    for (int off = 16; off > 0; off >>= 1) ss += __shfl_xor_sync(0xffffffffu, ss, off);
    float inv = 1.f / sqrtf(ss);
    float o = g0 * inv * pw[lane] + g1 * inv * pw[lane + 32];
#pragma unroll
    for (int off = 16; off > 0; off >>= 1) o += __shfl_xor_sync(0xffffffffu, o, off);
    if (lane == 0) out[b] = o + pb[0];
}

// ---------------- launch ----------------
extern "C" void kernel_launch(void* const* d_in, const int* in_sizes, int n_in,
                              void* d_out, int out_size) {
    const float* node_feat = (const float*)d_in[0];
    const float* cfg       = (const float*)d_in[1];
    const int*   opcode    = (const int*)d_in[2];
    const int*   eidx      = (const int*)d_in[3];
    const int*   batch     = (const int*)d_in[4];
    const float* op_emb    = (const float*)d_in[5];
    const float* type_emb  = (const float*)d_in[6];
    const float* lin_w     = (const float*)d_in[7];
    const float* lin_b     = (const float*)d_in[8];
    const float* post_w    = (const float*)d_in[9];
    const float* post_b    = (const float*)d_in[10];
    const float* wp[3] = {(const float*)d_in[11], (const float*)d_in[16], (const float*)d_in[21]};
    const float* bp[3] = {(const float*)d_in[12], (const float*)d_in[17], (const float*)d_in[22]};
    const float* wl[3] = {(const float*)d_in[13], (const float*)d_in[18], (const float*)d_in[23]};
    const float* bl[3] = {(const float*)d_in[14], (const float*)d_in[19], (const float*)d_in[24]};
    const float* wr[3] = {(const float*)d_in[15], (const float*)d_in[20], (const float*)d_in[25]};
    const int* src = eidx;
    const int* dst = eidx + E_EDGES;

    float *cat_, *x_, *xp_, *agg_, *xn_, *deg_, *wpad_, *wstk_, *gsum_, *cnt_;
    unsigned* gmax_;
    cudaGetSymbolAddress((void**)&cat_, g_cat);
    cudaGetSymbolAddress((void**)&x_,   g_x);
    cudaGetSymbolAddress((void**)&xp_,  g_xp);
    cudaGetSymbolAddress((void**)&agg_, g_agg);
    cudaGetSymbolAddress((void**)&xn_,  g_xn);
    cudaGetSymbolAddress((void**)&deg_, g_deg);
    cudaGetSymbolAddress((void**)&wpad_, g_wpad);
    cudaGetSymbolAddress((void**)&wstk_, g_wstk);
    cudaGetSymbolAddress((void**)&gmax_, g_gmax);
    cudaGetSymbolAddress((void**)&gsum_, g_gsum);
    cudaGetSymbolAddress((void**)&cnt_,  g_cnt);

    const int T = 256;
    const int GEMM_GRID = (N_NODES + 127) / 128;

    // weight prep + feature assembly
    pad_w_kernel<<<(PK * 128 + T - 1) / T, T>>>(lin_w);
    {
        size_t tot = (size_t)N_NODES * PK;
        embed_kernel<<<(unsigned)((tot + T - 1) / T), T>>>(node_feat, cfg, opcode, op_emb, type_emb);
    }

    // degree -> deg_inv
    zero_f<<<(N_NODES + T - 1) / T, T>>>(deg_, N_NODES);
    deg_kernel<<<(E_EDGES + T - 1) / T, T>>>(dst);
    deginv_kernel<<<(N_NODES + T - 1) / T, T>>>();

    // initial linear: x = relu(cat @ Wpad + b), (N,128)
    gemm_kernel<128, 8, true, false><<<GEMM_GRID, T>>>(cat_, PK, PK, cat_, PK, wpad_, lin_b, x_, 128, PK);

    const float* xin = x_;
    int ldx = 128;
    float* xout = xn_;
    for (int l = 0; l < 3; l++) {
        int D = (l == 0) ? 128 : 64;
        // xp = relu(x @ wp + bp), (N,D)
        if (D == 128)
            gemm_kernel<128, 8, true, false><<<GEMM_GRID, T>>>(xin, ldx, D, xin, ldx, wp[l], bp[l], xp_, D, D);
        else
            gemm_kernel<64, 4, true, false><<<GEMM_GRID, T>>>(xin, ldx, D, xin, ldx, wp[l], bp[l], xp_, D, D);
        // agg = scatter-mean(xp)
        {
            size_t nz = (size_t)N_NODES * D;
            zero_f<<<(unsigned)((nz + T - 1) / T), T>>>(agg_, nz);
            int D4 = D / 4;
            size_t tot = (size_t)E_EDGES * D4;
            scatter_kernel<<<(unsigned)((tot + T - 1) / T), T>>>(xp_, src, dst, agg_, D4);
        }
        // out = normalize( [agg | x] @ [wl; wr] + bl ), (N,64)
        stack_w_kernel<<<(2 * D * 64 + T - 1) / T, T>>>(wl[l], wr[l], D);
        gemm_kernel<64, 4, false, true><<<GEMM_GRID, T>>>(agg_, D, D, xin, ldx, wstk_, bl[l], xout, 64, 2 * D);
        xin = xout;
        ldx = 64;
        xout = (xout == xn_) ? x_ : xn_;
    }

    // pooling (FIX: proper grid for 1024-element accumulators; previously only
    // the first 256 were zeroed -> replay divergence)
    pool_init_kernel<<<(NBATCH * 64 + T - 1) / T, T>>>();
    {
        size_t tot = (size_t)N_NODES * 16;
        pool_kernel<<<(unsigned)((tot + T - 1) / T), T>>>(xin, batch);
    }
    final_kernel<<<1, 512>>>(post_w, post_b, (float*)d_out);
}

// round 5
// speedup vs baseline: 1.2717x; 1.2717x over previous
#include <cuda_runtime.h>
#include <math.h>
#include <stdint.h>

#define N_NODES 200000
#define E_EDGES 800000
#define NBATCH  16
#define PK      208   // 193 padded to multiple of 16

// ---------------- scratch (static; no cudaMalloc) ----------------
__device__ __align__(16) float    g_x   [(size_t)N_NODES * 128];
__device__ __align__(16) float    g_xp  [(size_t)N_NODES * 128];
__device__ __align__(16) float    g_aggA[(size_t)N_NODES * 64];
__device__ __align__(16) float    g_aggB[(size_t)N_NODES * 64];
__device__ __align__(16) float    g_y   [(size_t)N_NODES * 64];
__device__ __align__(16) float    g_rn  [N_NODES];
__device__ __align__(16) float    g_deg [N_NODES];
__device__ __align__(16) float    g_wpad[PK * 128];
__device__ __align__(16) unsigned g_gmax[NBATCH * 64];
__device__ __align__(16) float    g_gsum[NBATCH * 64];
__device__ __align__(16) float    g_cnt [NBATCH];

// ---------------- helpers ----------------
__device__ __forceinline__ unsigned fenc(float f) {
    unsigned u = __float_as_uint(f);
    return (u & 0x80000000u) ? ~u : (u | 0x80000000u);
}
__device__ __forceinline__ float fdec(unsigned u) {
    return (u & 0x80000000u) ? __uint_as_float(u & 0x7FFFFFFFu) : __uint_as_float(~u);
}

__global__ void zero_f(float* p, size_t n) {
    size_t i = (size_t)blockIdx.x * blockDim.x + threadIdx.x;
    if (i < n) p[i] = 0.f;
}

__global__ void pool_init_kernel() {
    int i = blockIdx.x * blockDim.x + threadIdx.x;
    if (i < NBATCH * 64) { g_gmax[i] = 0u; g_gsum[i] = 0.f; }
    if (i < NBATCH) g_cnt[i] = 0.f;
}

__global__ void pad_w_kernel(const float* __restrict__ lin_w) {
    int t = blockIdx.x * blockDim.x + threadIdx.x;
    if (t >= PK * 128) return;
    int k = t / 128, j = t % 128;
    g_wpad[t] = (k < 193) ? lin_w[k * 128 + j] : 0.f;
}

__global__ void deg_kernel(const int* __restrict__ dst) {
    int e = blockIdx.x * blockDim.x + threadIdx.x;
    if (e < E_EDGES) atomicAdd(&g_deg[dst[e]], 1.f);
}
__global__ void deginv_kernel() {
    int n = blockIdx.x * blockDim.x + threadIdx.x;
    if (n < N_NODES) g_deg[n] = 1.f / fmaxf(g_deg[n], 1.f);
}

// ---------------- fused feature gather ----------------
__device__ __forceinline__ float gatherA(const float* __restrict__ nf, const float* __restrict__ cfgf,
                                         const int* __restrict__ opc,
                                         const float* __restrict__ opE, const float* __restrict__ tyE,
                                         int n, int c) {
    if (c < 139) return nf[(size_t)n * 140 + c];
    if (c < 143) { int ty = (int)nf[(size_t)n * 140 + 139]; return tyE[ty * 4 + (c - 139)]; }
    if (c < 175) return opE[opc[n] * 32 + (c - 143)];
    if (c < 193) return cfgf[(size_t)n * 18 + (c - 175)];
    return 0.f;
}

// ---------------- initial GEMM: x = relu(gather(feat) @ Wpad + b), (N,128) ----
// Single-buffer, two syncs per K-tile (round-2 proven structure).
__global__ __launch_bounds__(256) void gemm_initial(
    const float* __restrict__ nf, const float* __restrict__ cfgf, const int* __restrict__ opc,
    const float* __restrict__ opE, const float* __restrict__ tyE,
    const float* __restrict__ bias, float* __restrict__ X)
{
    constexpr int BM = 128, BN = 128, BK = 16, TM = 8, TN = 8, TX = 16;
    __shared__ float As[BK][BM];
    __shared__ float Bs[BK][BN];
    const int tid = threadIdx.x, tx = tid % TX, ty = tid / TX;
    const int m0 = blockIdx.x * BM;
    float acc[TM][TN] = {};

    for (int k0 = 0; k0 < PK; k0 += BK) {
#pragma unroll
        for (int i = 0; i < 8; i++) {
            int idx = tid + i * 256; int m = idx / BK, k = idx % BK;
            int mg = m0 + m, kg = k0 + k;
            float v = 0.f;
            if (mg < N_NODES) v = gatherA(nf, cfgf, opc, opE, tyE, mg, kg);
            As[k][m] = v;
        }
#pragma unroll
        for (int i = 0; i < 8; i++) {
            int idx = tid + i * 256; int k = idx / BN, n = idx % BN;
            Bs[k][n] = g_wpad[(k0 + k) * BN + n];
        }
        __syncthreads();
#pragma unroll
        for (int kk = 0; kk < BK; kk++) {
            float ra[TM], rb[TN];
#pragma unroll
            for (int i = 0; i < TM; i += 4) {
                float4 a = *reinterpret_cast<const float4*>(&As[kk][ty * TM + i]);
                ra[i] = a.x; ra[i+1] = a.y; ra[i+2] = a.z; ra[i+3] = a.w;
            }
#pragma unroll
            for (int j = 0; j < TN; j += 4) {
                float4 b = *reinterpret_cast<const float4*>(&Bs[kk][tx * TN + j]);
                rb[j] = b.x; rb[j+1] = b.y; rb[j+2] = b.z; rb[j+3] = b.w;
            }
#pragma unroll
            for (int i = 0; i < TM; i++)
#pragma unroll
                for (int j = 0; j < TN; j++) acc[i][j] = fmaf(ra[i], rb[j], acc[i][j]);
        }
        __syncthreads();
    }
#pragma unroll
    for (int i = 0; i < TM; i++) {
        int mg = m0 + ty * TM + i;
        if (mg >= N_NODES) continue;
#pragma unroll
        for (int j = 0; j < TN; j += 4) {
            float4 o;
            o.x = fmaxf(acc[i][j+0] + bias[tx*TN+j+0], 0.f);
            o.y = fmaxf(acc[i][j+1] + bias[tx*TN+j+1], 0.f);
            o.z = fmaxf(acc[i][j+2] + bias[tx*TN+j+2], 0.f);
            o.w = fmaxf(acc[i][j+3] + bias[tx*TN+j+3], 0.f);
            *reinterpret_cast<float4*>(&X[(size_t)mg * 128 + tx * TN + j]) = o;
        }
    }
}

// ---------------- GEMM1: [xp | agg_init] = [relu(A@wp+bp) | A@wr+bl] --------
// A = Xin (N x IND), optionally per-row scaled by rn (fused L2-normalize).
template<int IND, bool HAS_RN>
__global__ __launch_bounds__(256) void gemm1_kernel(
    const float* __restrict__ Xin, const float* __restrict__ rn,
    const float* __restrict__ wp, const float* __restrict__ bp,
    const float* __restrict__ wr, const float* __restrict__ bl,
    float* __restrict__ xp, float* __restrict__ agg)
{
    constexpr int BM = 128, BN = IND + 64, BK = 16, TM = 8, TN = BN / 16, TX = 16;
    constexpr int BLOOP = BK * BN / 256;
    __shared__ float As[BK][BM];
    __shared__ float Bs[BK][BN];
    const int tid = threadIdx.x, tx = tid % TX, ty = tid / TX;
    const int m0 = blockIdx.x * BM;
    float acc[TM][TN] = {};

    for (int k0 = 0; k0 < IND; k0 += BK) {
#pragma unroll
        for (int i = 0; i < 8; i++) {
            int idx = tid + i * 256; int m = idx / BK, k = idx % BK;
            int mg = m0 + m, kg = k0 + k;
            float v = 0.f;
            if (mg < N_NODES) {
                v = Xin[(size_t)mg * IND + kg];
                if (HAS_RN) v *= rn[mg];
            }
            As[k][m] = v;
        }
#pragma unroll
        for (int i = 0; i < BLOOP; i++) {
            int idx = tid + i * 256; int k = idx / BN, n = idx % BN;
            int kg = k0 + k;
            Bs[k][n] = (n < IND) ? wp[kg * IND + n] : wr[kg * 64 + (n - IND)];
        }
        __syncthreads();
#pragma unroll
        for (int kk = 0; kk < BK; kk++) {
            float ra[TM], rb[TN];
#pragma unroll
            for (int i = 0; i < TM; i += 4) {
                float4 a = *reinterpret_cast<const float4*>(&As[kk][ty * TM + i]);
                ra[i] = a.x; ra[i+1] = a.y; ra[i+2] = a.z; ra[i+3] = a.w;
            }
#pragma unroll
            for (int j = 0; j < TN; j += 4) {
                float4 b = *reinterpret_cast<const float4*>(&Bs[kk][tx * TN + j]);
                rb[j] = b.x; rb[j+1] = b.y; rb[j+2] = b.z; rb[j+3] = b.w;
            }
#pragma unroll
            for (int i = 0; i < TM; i++)
#pragma unroll
                for (int j = 0; j < TN; j++) acc[i][j] = fmaf(ra[i], rb[j], acc[i][j]);
        }
        __syncthreads();
    }

    float bcol[TN];
#pragma unroll
    for (int j = 0; j < TN; j++) {
        int c = tx * TN + j;
        bcol[j] = (c < IND) ? bp[c] : bl[c - IND];
    }
#pragma unroll
    for (int i = 0; i < TM; i++) {
        int mg = m0 + ty * TM + i;
        if (mg >= N_NODES) continue;
#pragma unroll
        for (int j = 0; j < TN; j += 4) {
            int c0 = tx * TN + j;
            float4 o;
            o.x = acc[i][j+0] + bcol[j+0];
            o.y = acc[i][j+1] + bcol[j+1];
            o.z = acc[i][j+2] + bcol[j+2];
            o.w = acc[i][j+3] + bcol[j+3];
            if (c0 < IND) {
                o.x = fmaxf(o.x, 0.f); o.y = fmaxf(o.y, 0.f);
                o.z = fmaxf(o.z, 0.f); o.w = fmaxf(o.w, 0.f);
                *reinterpret_cast<float4*>(&xp[(size_t)mg * IND + c0]) = o;
            } else {
                *reinterpret_cast<float4*>(&agg[(size_t)mg * 64 + (c0 - IND)]) = o;
            }
        }
    }
}

// ---------------- GEMM2: y = xp @ wl, (N,64) ----------------
template<int IND>
__global__ __launch_bounds__(256) void gemm2_kernel(
    const float* __restrict__ xp, const float* __restrict__ wl, float* __restrict__ y)
{
    constexpr int BM = 128, BN = 64, BK = 16, TM = 8, TN = 4, TX = 16;
    __shared__ float As[BK][BM];
    __shared__ float Bs[BK][BN];
    const int tid = threadIdx.x, tx = tid % TX, ty = tid / TX;
    const int m0 = blockIdx.x * BM;
    float acc[TM][TN] = {};

    for (int k0 = 0; k0 < IND; k0 += BK) {
#pragma unroll
        for (int i = 0; i < 8; i++) {
            int idx = tid + i * 256; int m = idx / BK, k = idx % BK;
            int mg = m0 + m, kg = k0 + k;
            As[k][m] = (mg < N_NODES) ? xp[(size_t)mg * IND + kg] : 0.f;
        }
#pragma unroll
        for (int i = 0; i < 4; i++) {
            int idx = tid + i * 256; int k = idx / BN, n = idx % BN;
            Bs[k][n] = wl[(k0 + k) * 64 + n];
        }
        __syncthreads();
#pragma unroll
        for (int kk = 0; kk < BK; kk++) {
            float ra[TM], rb[TN];
#pragma unroll
            for (int i = 0; i < TM; i += 4) {
                float4 a = *reinterpret_cast<const float4*>(&As[kk][ty * TM + i]);
                ra[i] = a.x; ra[i+1] = a.y; ra[i+2] = a.z; ra[i+3] = a.w;
            }
            float4 b = *reinterpret_cast<const float4*>(&Bs[kk][tx * TN]);
            rb[0] = b.x; rb[1] = b.y; rb[2] = b.z; rb[3] = b.w;
#pragma unroll
            for (int i = 0; i < TM; i++)
#pragma unroll
                for (int j = 0; j < TN; j++) acc[i][j] = fmaf(ra[i], rb[j], acc[i][j]);
        }
        __syncthreads();
    }
#pragma unroll
    for (int i = 0; i < TM; i++) {
        int mg = m0 + ty * TM + i;
        if (mg >= N_NODES) continue;
        float4 o = make_float4(acc[i][0], acc[i][1], acc[i][2], acc[i][3]);
        *reinterpret_cast<float4*>(&y[(size_t)mg * 64 + tx * TN]) = o;
    }
}

// ---------------- scatter: agg[dst] += y[src] * deg_inv[dst], 64-wide -------
__global__ void scatter_kernel(const float* __restrict__ y, const int* __restrict__ src,
                               const int* __restrict__ dst, float* __restrict__ agg) {
    size_t t = (size_t)blockIdx.x * blockDim.x + threadIdx.x;
    if (t >= (size_t)E_EDGES * 16) return;
    int e = (int)(t >> 4), q = (int)(t & 15);
    int s = src[e], d = dst[e];
    float4 v = reinterpret_cast<const float4*>(y)[(size_t)s * 16 + q];
    float di = g_deg[d];
    float* p = agg + (size_t)d * 64 + q * 4;
    asm volatile("red.global.add.v4.f32 [%0], {%1,%2,%3,%4};"
                 :: "l"(p), "f"(v.x * di), "f"(v.y * di), "f"(v.z * di), "f"(v.w * di)
                 : "memory");
}

// ---------------- per-row inverse L2 norm ----------------
__global__ void rownorm_kernel(const float* __restrict__ agg) {
    int gw = (blockIdx.x * blockDim.x + threadIdx.x) >> 5;
    int lane = threadIdx.x & 31;
    if (gw >= N_NODES) return;
    float a = agg[(size_t)gw * 64 + lane];
    float b = agg[(size_t)gw * 64 + lane + 32];
    float ss = a * a + b * b;
#pragma unroll
    for (int off = 16; off > 0; off >>= 1) ss += __shfl_xor_sync(0xffffffffu, ss, off);
    if (lane == 0) g_rn[gw] = 1.f / fmaxf(sqrtf(ss), 1e-12f);
}

// ---------------- pooling: direct global atomics (round-2 proven) ----------
// reads normalized value = agg[n][c] * rn[n]
__global__ void pool_kernel(const float* __restrict__ agg, const float* __restrict__ rn,
                            const int* __restrict__ batch) {
    size_t t = (size_t)blockIdx.x * blockDim.x + threadIdx.x;
    if (t >= (size_t)N_NODES * 16) return;
    int n = (int)(t >> 4), q = (int)(t & 15);
    int b = batch[n];
    float4 v = reinterpret_cast<const float4*>(agg)[(size_t)n * 16 + q];
    float r = rn[n];
    v.x *= r; v.y *= r; v.z *= r; v.w *= r;
    int base = b * 64 + q * 4;
    atomicMax(&g_gmax[base + 0], fenc(v.x));
    atomicMax(&g_gmax[base + 1], fenc(v.y));
    atomicMax(&g_gmax[base + 2], fenc(v.z));
    atomicMax(&g_gmax[base + 3], fenc(v.w));
    atomicAdd(&g_gsum[base + 0], v.x);
    atomicAdd(&g_gsum[base + 1], v.y);
    atomicAdd(&g_gsum[base + 2], v.z);
    atomicAdd(&g_gsum[base + 3], v.w);
    if (q == 0) atomicAdd(&g_cnt[b], 1.f);
}

__global__ void final_kernel(const float* __restrict__ pw, const float* __restrict__ pb,
                             float* __restrict__ out) {
    int b = threadIdx.x / 32, lane = threadIdx.x % 32;
    if (b >= NBATCH) return;
    float c = fmaxf(g_cnt[b], 1.f);
    float g0 = fdec(g_gmax[b * 64 + lane])      + g_gsum[b * 64 + lane] / c;
    float g1 = fdec(g_gmax[b * 64 + lane + 32]) + g_gsum[b * 64 + lane + 32] / c;
    float ss = g0 * g0 + g1 * g1;
#pragma unroll
    for (int off = 16; off > 0; off >>= 1) ss += __shfl_xor_sync(0xffffffffu, ss, off);
    float inv = 1.f / sqrtf(ss);
    float o = g0 * inv * pw[lane] + g1 * inv * pw[lane + 32];
#pragma unroll
    for (int off = 16; off > 0; off >>= 1) o += __shfl_xor_sync(0xffffffffu, o, off);
    if (lane == 0) out[b] = o + pb[0];
}

// ---------------- launch ----------------
extern "C" void kernel_launch(void* const* d_in, const int* in_sizes, int n_in,
                              void* d_out, int out_size) {
    const float* node_feat = (const float*)d_in[0];
    const float* cfg       = (const float*)d_in[1];
    const int*   opcode    = (const int*)d_in[2];
    const int*   eidx      = (const int*)d_in[3];
    const int*   batch     = (const int*)d_in[4];
    const float* op_emb    = (const float*)d_in[5];
    const float* type_emb  = (const float*)d_in[6];
    const float* lin_w     = (const float*)d_in[7];
    const float* lin_b     = (const float*)d_in[8];
    const float* post_w    = (const float*)d_in[9];
    const float* post_b    = (const float*)d_in[10];
    const float* wp[3] = {(const float*)d_in[11], (const float*)d_in[16], (const float*)d_in[21]};
    const float* bp[3] = {(const float*)d_in[12], (const float*)d_in[17], (const float*)d_in[22]};
    const float* wl[3] = {(const float*)d_in[13], (const float*)d_in[18], (const float*)d_in[23]};
    const float* bl[3] = {(const float*)d_in[14], (const float*)d_in[19], (const float*)d_in[24]};
    const float* wr[3] = {(const float*)d_in[15], (const float*)d_in[20], (const float*)d_in[25]};
    const int* src = eidx;
    const int* dst = eidx + E_EDGES;

    float *x_, *xp_, *aggA_, *aggB_, *y_, *rn_, *deg_;
    cudaGetSymbolAddress((void**)&x_,    g_x);
    cudaGetSymbolAddress((void**)&xp_,   g_xp);
    cudaGetSymbolAddress((void**)&aggA_, g_aggA);
    cudaGetSymbolAddress((void**)&aggB_, g_aggB);
    cudaGetSymbolAddress((void**)&y_,    g_y);
    cudaGetSymbolAddress((void**)&rn_,   g_rn);
    cudaGetSymbolAddress((void**)&deg_,  g_deg);

    const int T = 256;
    const int GEMM_GRID = (N_NODES + 127) / 128;
    const unsigned SCAT_GRID = (unsigned)(((size_t)E_EDGES * 16 + T - 1) / T);
    const unsigned WARP_GRID = (unsigned)(((size_t)N_NODES * 32 + T - 1) / T);
    const unsigned POOL_GRID = (unsigned)(((size_t)N_NODES * 16 + T - 1) / T);

    pad_w_kernel<<<(PK * 128 + T - 1) / T, T>>>(lin_w);
    zero_f<<<(N_NODES + T - 1) / T, T>>>(deg_, N_NODES);
    deg_kernel<<<(E_EDGES + T - 1) / T, T>>>(dst);
    deginv_kernel<<<(N_NODES + T - 1) / T, T>>>();
    pool_init_kernel<<<(NBATCH * 64 + T - 1) / T, T>>>();

    gemm_initial<<<GEMM_GRID, T>>>(node_feat, cfg, opcode, op_emb, type_emb, lin_b, x_);

    // layer 0 (IND=128)
    gemm1_kernel<128, false><<<GEMM_GRID, T>>>(x_, nullptr, wp[0], bp[0], wr[0], bl[0], xp_, aggA_);
    gemm2_kernel<128><<<GEMM_GRID, T>>>(xp_, wl[0], y_);
    scatter_kernel<<<SCAT_GRID, T>>>(y_, src, dst, aggA_);
    rownorm_kernel<<<WARP_GRID, T>>>(aggA_);

    // layer 1 (IND=64)
    gemm1_kernel<64, true><<<GEMM_GRID, T>>>(aggA_, rn_, wp[1], bp[1], wr[1], bl[1], xp_, aggB_);
    gemm2_kernel<64><<<GEMM_GRID, T>>>(xp_, wl[1], y_);
    scatter_kernel<<<SCAT_GRID, T>>>(y_, src, dst, aggB_);
    rownorm_kernel<<<WARP_GRID, T>>>(aggB_);

    // layer 2 (IND=64)
    gemm1_kernel<64, true><<<GEMM_GRID, T>>>(aggB_, rn_, wp[2], bp[2], wr[2], bl[2], xp_, aggA_);
    gemm2_kernel<64><<<GEMM_GRID, T>>>(xp_, wl[2], y_);
    scatter_kernel<<<SCAT_GRID, T>>>(y_, src, dst, aggA_);
    rownorm_kernel<<<WARP_GRID, T>>>(aggA_);

    // pooling on normalized layer-2 output
    pool_kernel<<<POOL_GRID, T>>>(aggA_, rn_, batch);
    final_kernel<<<1, 512>>>(post_w, post_b, (float*)d_out);
}

// round 6
// speedup vs baseline: 1.3588x; 1.0685x over previous
#include <cuda_runtime.h>
#include <math.h>
#include <stdint.h>

#define N_NODES 200000
#define E_EDGES 800000
#define NBATCH  16
#define PK      208   // 193 padded to multiple of 16

// ---------------- scratch (static; no cudaMalloc) ----------------
__device__ __align__(16) float    g_x   [(size_t)N_NODES * 128];
__device__ __align__(16) float    g_xp  [(size_t)N_NODES * 128];
__device__ __align__(16) float    g_aggA[(size_t)N_NODES * 64];
__device__ __align__(16) float    g_aggB[(size_t)N_NODES * 64];
__device__ __align__(16) float    g_y   [(size_t)N_NODES * 64];
__device__ __align__(16) float    g_rn  [N_NODES];
__device__ __align__(16) float    g_deg [N_NODES];
__device__ __align__(16) float    g_wpad[PK * 128];
__device__ __align__(16) unsigned g_gmax[NBATCH * 64];
__device__ __align__(16) float    g_gsum[NBATCH * 64];
__device__ __align__(16) float    g_cnt [NBATCH];

// ---------------- helpers ----------------
__device__ __forceinline__ unsigned fenc(float f) {
    unsigned u = __float_as_uint(f);
    return (u & 0x80000000u) ? ~u : (u | 0x80000000u);
}
__device__ __forceinline__ float fdec(unsigned u) {
    return (u & 0x80000000u) ? __uint_as_float(u & 0x7FFFFFFFu) : __uint_as_float(~u);
}

__global__ void zero_f(float* p, size_t n) {
    size_t i = (size_t)blockIdx.x * blockDim.x + threadIdx.x;
    if (i < n) p[i] = 0.f;
}

__global__ void pool_init_kernel() {
    int i = blockIdx.x * blockDim.x + threadIdx.x;
    if (i < NBATCH * 64) { g_gmax[i] = 0u; g_gsum[i] = 0.f; }
    if (i < NBATCH) g_cnt[i] = 0.f;
}

__global__ void pad_w_kernel(const float* __restrict__ lin_w) {
    int t = blockIdx.x * blockDim.x + threadIdx.x;
    if (t >= PK * 128) return;
    int k = t / 128, j = t % 128;
    g_wpad[t] = (k < 193) ? lin_w[k * 128 + j] : 0.f;
}

__global__ void deg_kernel(const int* __restrict__ dst) {
    int e = blockIdx.x * blockDim.x + threadIdx.x;
    if (e < E_EDGES) atomicAdd(&g_deg[dst[e]], 1.f);
}
__global__ void deginv_kernel() {
    int n = blockIdx.x * blockDim.x + threadIdx.x;
    if (n < N_NODES) g_deg[n] = 1.f / fmaxf(g_deg[n], 1.f);
}

// ---------------- tf32 split helpers ----------------
__device__ __forceinline__ void split_tf32(float x, uint32_t& h, uint32_t& l) {
    uint32_t hb;
    asm("cvt.rna.tf32.f32 %0, %1;" : "=r"(hb) : "f"(x));
    h = hb;
    l = __float_as_uint(x - __uint_as_float(hb));
}

__device__ __forceinline__ void mma8(float* c, const uint32_t* a, const uint32_t* b) {
    asm("mma.sync.aligned.m16n8k8.row.col.f32.tf32.tf32.f32 "
        "{%0,%1,%2,%3}, {%4,%5,%6,%7}, {%8,%9}, {%0,%1,%2,%3};"
        : "+f"(c[0]), "+f"(c[1]), "+f"(c[2]), "+f"(c[3])
        : "r"(a[0]), "r"(a[1]), "r"(a[2]), "r"(a[3]), "r"(b[0]), "r"(b[1]));
}

// swizzled indices (conflict-free fragment reads)
__device__ __forceinline__ int idxA(int k, int m) { return k * 128 + (m ^ ((k & 3) << 3)); }
template<int BN>
__device__ __forceinline__ int idxB(int k, int n) { return k * BN + (n ^ ((k & 3) << 3)); }

// one BK=16 tile of split-tf32 mma: acc += As @ B(hi+lo)
template<int BN, int NI>
__device__ __forceinline__ void mma_ktile(const float* As, const uint32_t* Bh, const uint32_t* Bl,
                                          int wm, int wn, int gid, int tig,
                                          float (&acc)[2][NI][4]) {
#pragma unroll
    for (int kk = 0; kk < 2; kk++) {
        const int kb = kk * 8 + tig;
        uint32_t aH[2][4], aL[2][4];
#pragma unroll
        for (int mi = 0; mi < 2; mi++) {
            int r = wm + mi * 16 + gid;
            split_tf32(As[idxA(kb,     r    )], aH[mi][0], aL[mi][0]);
            split_tf32(As[idxA(kb,     r + 8)], aH[mi][1], aL[mi][1]);
            split_tf32(As[idxA(kb + 4, r    )], aH[mi][2], aL[mi][2]);
            split_tf32(As[idxA(kb + 4, r + 8)], aH[mi][3], aL[mi][3]);
        }
#pragma unroll
        for (int ni = 0; ni < NI; ni++) {
            int n = wn + ni * 8 + gid;
            uint32_t bh[2], bl[2];
            bh[0] = Bh[idxB<BN>(kb, n)];     bh[1] = Bh[idxB<BN>(kb + 4, n)];
            bl[0] = Bl[idxB<BN>(kb, n)];     bl[1] = Bl[idxB<BN>(kb + 4, n)];
#pragma unroll
            for (int mi = 0; mi < 2; mi++) {
                mma8(acc[mi][ni], aH[mi], bh);
                mma8(acc[mi][ni], aH[mi], bl);
                mma8(acc[mi][ni], aL[mi], bh);
            }
        }
    }
}

// ---------------- fused feature gather ----------------
__device__ __forceinline__ float gatherA(const float* __restrict__ nf, const float* __restrict__ cfgf,
                                         const int* __restrict__ opc,
                                         const float* __restrict__ opE, const float* __restrict__ tyE,
                                         int n, int c) {
    if (c < 139) return nf[(size_t)n * 140 + c];
    if (c < 143) { int ty = (int)nf[(size_t)n * 140 + 139]; return tyE[ty * 4 + (c - 139)]; }
    if (c < 175) return opE[opc[n] * 32 + (c - 143)];
    if (c < 193) return cfgf[(size_t)n * 18 + (c - 175)];
    return 0.f;
}

// ---------------- initial GEMM: x = relu(gather(feat) @ Wpad + b), (N,128) ----
__global__ __launch_bounds__(256) void gemm_initial(
    const float* __restrict__ nf, const float* __restrict__ cfgf, const int* __restrict__ opc,
    const float* __restrict__ opE, const float* __restrict__ tyE,
    const float* __restrict__ bias, float* __restrict__ X)
{
    constexpr int BN = 128, NI = 8;
    __shared__ float    As[16 * 128];
    __shared__ uint32_t Bh[16 * BN];
    __shared__ uint32_t Bl[16 * BN];
    const int tid = threadIdx.x, lane = tid & 31, wid = tid >> 5;
    const int gid = lane >> 2, tig = lane & 3;
    const int wm = (wid & 3) * 32, wn = (wid >> 2) * (BN / 2);
    const int m0 = blockIdx.x * 128;
    float acc[2][NI][4] = {};

    for (int k0 = 0; k0 < PK; k0 += 16) {
#pragma unroll
        for (int i = 0; i < 8; i++) {
            int idx = tid + i * 256; int m = idx >> 4, k = idx & 15;
            int mg = m0 + m, kg = k0 + k;
            float v = (mg < N_NODES) ? gatherA(nf, cfgf, opc, opE, tyE, mg, kg) : 0.f;
            As[idxA(k, m)] = v;
        }
#pragma unroll
        for (int i = 0; i < 8; i++) {
            int idx = tid + i * 256; int k = idx / BN, n = idx % BN;
            uint32_t h, l;
            split_tf32(g_wpad[(k0 + k) * 128 + n], h, l);
            Bh[idxB<BN>(k, n)] = h; Bl[idxB<BN>(k, n)] = l;
        }
        __syncthreads();
        mma_ktile<BN, NI>(As, Bh, Bl, wm, wn, gid, tig, acc);
        __syncthreads();
    }

#pragma unroll
    for (int mi = 0; mi < 2; mi++) {
        int r0 = m0 + wm + mi * 16 + gid;
#pragma unroll
        for (int ni = 0; ni < NI; ni++) {
            int c = wn + ni * 8 + 2 * tig;
            float b0 = bias[c], b1 = bias[c + 1];
            if (r0 < N_NODES) {
                float2 o = make_float2(fmaxf(acc[mi][ni][0] + b0, 0.f),
                                       fmaxf(acc[mi][ni][1] + b1, 0.f));
                *reinterpret_cast<float2*>(&X[(size_t)r0 * 128 + c]) = o;
            }
            if (r0 + 8 < N_NODES) {
                float2 o = make_float2(fmaxf(acc[mi][ni][2] + b0, 0.f),
                                       fmaxf(acc[mi][ni][3] + b1, 0.f));
                *reinterpret_cast<float2*>(&X[(size_t)(r0 + 8) * 128 + c]) = o;
            }
        }
    }
}

// ---------------- GEMM1: [xp | agg_init] = [relu(A@wp+bp) | A@wr+bl] --------
template<int IND, bool HAS_RN>
__global__ __launch_bounds__(256) void gemm1_kernel(
    const float* __restrict__ Xin, const float* __restrict__ rn,
    const float* __restrict__ wp, const float* __restrict__ bp,
    const float* __restrict__ wr, const float* __restrict__ bl,
    float* __restrict__ xp, float* __restrict__ agg)
{
    constexpr int BN = IND + 64, NI = BN / 16;
    __shared__ float    As[16 * 128];
    __shared__ uint32_t Bh[16 * BN];
    __shared__ uint32_t Bl[16 * BN];
    const int tid = threadIdx.x, lane = tid & 31, wid = tid >> 5;
    const int gid = lane >> 2, tig = lane & 3;
    const int wm = (wid & 3) * 32, wn = (wid >> 2) * (BN / 2);
    const int m0 = blockIdx.x * 128;
    float acc[2][NI][4] = {};

    for (int k0 = 0; k0 < IND; k0 += 16) {
#pragma unroll
        for (int i = 0; i < 8; i++) {
            int idx = tid + i * 256; int m = idx >> 4, k = idx & 15;
            int mg = m0 + m, kg = k0 + k;
            float v = 0.f;
            if (mg < N_NODES) {
                v = Xin[(size_t)mg * IND + kg];
                if (HAS_RN) v *= rn[mg];
            }
            As[idxA(k, m)] = v;
        }
#pragma unroll
        for (int i = 0; i < BN / 16; i++) {   // 16*BN/256
            int idx = tid + i * 256; int k = idx / BN, n = idx % BN;
            int kg = k0 + k;
            float v = (n < IND) ? wp[kg * IND + n] : wr[kg * 64 + (n - IND)];
            uint32_t h, l; split_tf32(v, h, l);
            Bh[idxB<BN>(k, n)] = h; Bl[idxB<BN>(k, n)] = l;
        }
        __syncthreads();
        mma_ktile<BN, NI>(As, Bh, Bl, wm, wn, gid, tig, acc);
        __syncthreads();
    }

#pragma unroll
    for (int mi = 0; mi < 2; mi++) {
        int r0 = m0 + wm + mi * 16 + gid;
#pragma unroll
        for (int ni = 0; ni < NI; ni++) {
            int c = wn + ni * 8 + 2 * tig;
            float b0, b1;
            if (c < IND) { b0 = bp[c]; b1 = bp[c + 1]; }
            else         { b0 = bl[c - IND]; b1 = bl[c - IND + 1]; }
#pragma unroll
            for (int h = 0; h < 2; h++) {
                int r = r0 + h * 8;
                if (r >= N_NODES) continue;
                float v0 = acc[mi][ni][2 * h]     + b0;
                float v1 = acc[mi][ni][2 * h + 1] + b1;
                if (c < IND) {
                    float2 o = make_float2(fmaxf(v0, 0.f), fmaxf(v1, 0.f));
                    *reinterpret_cast<float2*>(&xp[(size_t)r * IND + c]) = o;
                } else {
                    float2 o = make_float2(v0, v1);
                    *reinterpret_cast<float2*>(&agg[(size_t)r * 64 + (c - IND)]) = o;
                }
            }
        }
    }
}

// ---------------- GEMM2: y = xp @ wl, (N,64) ----------------
template<int IND>
__global__ __launch_bounds__(256) void gemm2_kernel(
    const float* __restrict__ xp, const float* __restrict__ wl, float* __restrict__ y)
{
    constexpr int BN = 64, NI = 4;
    __shared__ float    As[16 * 128];
    __shared__ uint32_t Bh[16 * BN];
    __shared__ uint32_t Bl[16 * BN];
    const int tid = threadIdx.x, lane = tid & 31, wid = tid >> 5;
    const int gid = lane >> 2, tig = lane & 3;
    const int wm = (wid & 3) * 32, wn = (wid >> 2) * 32;
    const int m0 = blockIdx.x * 128;
    float acc[2][NI][4] = {};

    for (int k0 = 0; k0 < IND; k0 += 16) {
#pragma unroll
        for (int i = 0; i < 8; i++) {
            int idx = tid + i * 256; int m = idx >> 4, k = idx & 15;
            int mg = m0 + m, kg = k0 + k;
            As[idxA(k, m)] = (mg < N_NODES) ? xp[(size_t)mg * IND + kg] : 0.f;
        }
#pragma unroll
        for (int i = 0; i < 4; i++) {
            int idx = tid + i * 256; int k = idx / BN, n = idx % BN;
            uint32_t h, l; split_tf32(wl[(k0 + k) * 64 + n], h, l);
            Bh[idxB<BN>(k, n)] = h; Bl[idxB<BN>(k, n)] = l;
        }
        __syncthreads();
        mma_ktile<BN, NI>(As, Bh, Bl, wm, wn, gid, tig, acc);
        __syncthreads();
    }

#pragma unroll
    for (int mi = 0; mi < 2; mi++) {
        int r0 = m0 + wm + mi * 16 + gid;
#pragma unroll
        for (int ni = 0; ni < NI; ni++) {
            int c = wn + ni * 8 + 2 * tig;
            if (r0 < N_NODES) {
                float2 o = make_float2(acc[mi][ni][0], acc[mi][ni][1]);
                *reinterpret_cast<float2*>(&y[(size_t)r0 * 64 + c]) = o;
            }
            if (r0 + 8 < N_NODES) {
                float2 o = make_float2(acc[mi][ni][2], acc[mi][ni][3]);
                *reinterpret_cast<float2*>(&y[(size_t)(r0 + 8) * 64 + c]) = o;
            }
        }
    }
}

// ---------------- scatter: agg[dst] += y[src] * deg_inv[dst], 64-wide -------
__global__ void scatter_kernel(const float* __restrict__ y, const int* __restrict__ src,
                               const int* __restrict__ dst, float* __restrict__ agg) {
    size_t t = (size_t)blockIdx.x * blockDim.x + threadIdx.x;
    if (t >= (size_t)E_EDGES * 16) return;
    int e = (int)(t >> 4), q = (int)(t & 15);
    int s = src[e], d = dst[e];
    float4 v = reinterpret_cast<const float4*>(y)[(size_t)s * 16 + q];
    float di = g_deg[d];
    float* p = agg + (size_t)d * 64 + q * 4;
    asm volatile("red.global.add.v4.f32 [%0], {%1,%2,%3,%4};"
                 :: "l"(p), "f"(v.x * di), "f"(v.y * di), "f"(v.z * di), "f"(v.w * di)
                 : "memory");
}

// ---------------- per-row inverse L2 norm ----------------
__global__ void rownorm_kernel(const float* __restrict__ agg) {
    int gw = (blockIdx.x * blockDim.x + threadIdx.x) >> 5;
    int lane = threadIdx.x & 31;
    if (gw >= N_NODES) return;
    float a = agg[(size_t)gw * 64 + lane];
    float b = agg[(size_t)gw * 64 + lane + 32];
    float ss = a * a + b * b;
#pragma unroll
    for (int off = 16; off > 0; off >>= 1) ss += __shfl_xor_sync(0xffffffffu, ss, off);
    if (lane == 0) g_rn[gw] = 1.f / fmaxf(sqrtf(ss), 1e-12f);
}

// ---------------- pooling: direct global atomics ----------
__global__ void pool_kernel(const float* __restrict__ agg, const float* __restrict__ rn,
                            const int* __restrict__ batch) {
    size_t t = (size_t)blockIdx.x * blockDim.x + threadIdx.x;
    if (t >= (size_t)N_NODES * 16) return;
    int n = (int)(t >> 4), q = (int)(t & 15);
    int b = batch[n];
    float4 v = reinterpret_cast<const float4*>(agg)[(size_t)n * 16 + q];
    float r = rn[n];
    v.x *= r; v.y *= r; v.z *= r; v.w *= r;
    int base = b * 64 + q * 4;
    atomicMax(&g_gmax[base + 0], fenc(v.x));
    atomicMax(&g_gmax[base + 1], fenc(v.y));
    atomicMax(&g_gmax[base + 2], fenc(v.z));
    atomicMax(&g_gmax[base + 3], fenc(v.w));
    atomicAdd(&g_gsum[base + 0], v.x);
    atomicAdd(&g_gsum[base + 1], v.y);
    atomicAdd(&g_gsum[base + 2], v.z);
    atomicAdd(&g_gsum[base + 3], v.w);
    if (q == 0) atomicAdd(&g_cnt[b], 1.f);
}

__global__ void final_kernel(const float* __restrict__ pw, const float* __restrict__ pb,
                             float* __restrict__ out) {
    int b = threadIdx.x / 32, lane = threadIdx.x % 32;
    if (b >= NBATCH) return;
    float c = fmaxf(g_cnt[b], 1.f);
    float g0 = fdec(g_gmax[b * 64 + lane])      + g_gsum[b * 64 + lane] / c;
    float g1 = fdec(g_gmax[b * 64 + lane + 32]) + g_gsum[b * 64 + lane + 32] / c;
    float ss = g0 * g0 + g1 * g1;
#pragma unroll
    for (int off = 16; off > 0; off >>= 1) ss += __shfl_xor_sync(0xffffffffu, ss, off);
    float inv = 1.f / sqrtf(ss);
    float o = g0 * inv * pw[lane] + g1 * inv * pw[lane + 32];
#pragma unroll
    for (int off = 16; off > 0; off >>= 1) o += __shfl_xor_sync(0xffffffffu, o, off);
    if (lane == 0) out[b] = o + pb[0];
}

// ---------------- launch ----------------
extern "C" void kernel_launch(void* const* d_in, const int* in_sizes, int n_in,
                              void* d_out, int out_size) {
    const float* node_feat = (const float*)d_in[0];
    const float* cfg       = (const float*)d_in[1];
    const int*   opcode    = (const int*)d_in[2];
    const int*   eidx      = (const int*)d_in[3];
    const int*   batch     = (const int*)d_in[4];
    const float* op_emb    = (const float*)d_in[5];
    const float* type_emb  = (const float*)d_in[6];
    const float* lin_w     = (const float*)d_in[7];
    const float* lin_b     = (const float*)d_in[8];
    const float* post_w    = (const float*)d_in[9];
    const float* post_b    = (const float*)d_in[10];
    const float* wp[3] = {(const float*)d_in[11], (const float*)d_in[16], (const float*)d_in[21]};
    const float* bp[3] = {(const float*)d_in[12], (const float*)d_in[17], (const float*)d_in[22]};
    const float* wl[3] = {(const float*)d_in[13], (const float*)d_in[18], (const float*)d_in[23]};
    const float* bl[3] = {(const float*)d_in[14], (const float*)d_in[19], (const float*)d_in[24]};
    const float* wr[3] = {(const float*)d_in[15], (const float*)d_in[20], (const float*)d_in[25]};
    const int* src = eidx;
    const int* dst = eidx + E_EDGES;

    float *x_, *xp_, *aggA_, *aggB_, *y_, *rn_, *deg_;
    cudaGetSymbolAddress((void**)&x_,    g_x);
    cudaGetSymbolAddress((void**)&xp_,   g_xp);
    cudaGetSymbolAddress((void**)&aggA_, g_aggA);
    cudaGetSymbolAddress((void**)&aggB_, g_aggB);
    cudaGetSymbolAddress((void**)&y_,    g_y);
    cudaGetSymbolAddress((void**)&rn_,   g_rn);
    cudaGetSymbolAddress((void**)&deg_,  g_deg);

    const int T = 256;
    const int GEMM_GRID = (N_NODES + 127) / 128;
    const unsigned SCAT_GRID = (unsigned)(((size_t)E_EDGES * 16 + T - 1) / T);
    const unsigned WARP_GRID = (unsigned)(((size_t)N_NODES * 32 + T - 1) / T);
    const unsigned POOL_GRID = (unsigned)(((size_t)N_NODES * 16 + T - 1) / T);

    pad_w_kernel<<<(PK * 128 + T - 1) / T, T>>>(lin_w);
    zero_f<<<(N_NODES + T - 1) / T, T>>>(deg_, N_NODES);
    deg_kernel<<<(E_EDGES + T - 1) / T, T>>>(dst);
    deginv_kernel<<<(N_NODES + T - 1) / T, T>>>();
    pool_init_kernel<<<(NBATCH * 64 + T - 1) / T, T>>>();

    gemm_initial<<<GEMM_GRID, T>>>(node_feat, cfg, opcode, op_emb, type_emb, lin_b, x_);

    // layer 0 (IND=128)
    gemm1_kernel<128, false><<<GEMM_GRID, T>>>(x_, nullptr, wp[0], bp[0], wr[0], bl[0], xp_, aggA_);
    gemm2_kernel<128><<<GEMM_GRID, T>>>(xp_, wl[0], y_);
    scatter_kernel<<<SCAT_GRID, T>>>(y_, src, dst, aggA_);
    rownorm_kernel<<<WARP_GRID, T>>>(aggA_);

    // layer 1 (IND=64)
    gemm1_kernel<64, true><<<GEMM_GRID, T>>>(aggA_, rn_, wp[1], bp[1], wr[1], bl[1], xp_, aggB_);
    gemm2_kernel<64><<<GEMM_GRID, T>>>(xp_, wl[1], y_);
    scatter_kernel<<<SCAT_GRID, T>>>(y_, src, dst, aggB_);
    rownorm_kernel<<<WARP_GRID, T>>>(aggB_);

    // layer 2 (IND=64)
    gemm1_kernel<64, true><<<GEMM_GRID, T>>>(aggB_, rn_, wp[2], bp[2], wr[2], bl[2], xp_, aggA_);
    gemm2_kernel<64><<<GEMM_GRID, T>>>(xp_, wl[2], y_);
    scatter_kernel<<<SCAT_GRID, T>>>(y_, src, dst, aggA_);
    rownorm_kernel<<<WARP_GRID, T>>>(aggA_);

    // pooling on normalized layer-2 output
    pool_kernel<<<POOL_GRID, T>>>(aggA_, rn_, batch);
    final_kernel<<<1, 512>>>(post_w, post_b, (float*)d_out);
}